// round 3
// baseline (speedup 1.0000x reference)
#include <cuda_runtime.h>
#include <cstdint>
#include <cstddef>

// ---------------------------------------------------------------------------
// Problem constants
// ---------------------------------------------------------------------------
constexpr int B_ = 256;   // batches
constexpr int N_ = 1024;  // patches
constexpr int M_ = 128;   // words
constexpr int C_ = 512;   // channels (K)

constexpr int NTILE  = 128;          // patch tile per iteration
constexpr int NTILES = N_ / NTILE;   // 8
constexpr int KC     = 32;           // K chunk
constexpr int KCH    = C_ / KC;      // 16
constexpr int GTOT   = NTILES * KCH; // 128 chunks
constexpr int SP     = 36;           // smem row stride (floats), bank-conflict-free

// SMEM layout in floats (dynamic shared)
constexpr int OFF_A0       = 0;                      // A tile buf (128 x SP)
constexpr int OFF_B0       = 128 * SP;               // B tile buf
constexpr int BUF_FLOATS   = 2 * 128 * SP;           // 9216 per buffer
constexpr int OFF_MASK     = 2 * BUF_FLOATS;         // 18432 (+1024)
constexpr int OFF_COLW     = OFF_MASK + 1024;        // 4 x 128
constexpr int OFF_ROWRED   = OFF_COLW + 4 * 128;     // 128 x 2
constexpr int OFF_RED      = OFF_ROWRED + 256;       // 32
constexpr int SMEM_FLOATS  = OFF_RED + 32;           // 20256
constexpr int SMEM_BYTES   = SMEM_FLOATS * 4;        // 81024

// ---------------------------------------------------------------------------
// Helpers
// ---------------------------------------------------------------------------
__device__ __forceinline__ uint32_t smem_u32(const void* p) {
    uint32_t a;
    asm("{ .reg .u64 t; cvta.to.shared.u64 t, %1; cvt.u32.u64 %0, t; }"
        : "=r"(a) : "l"(p));
    return a;
}

__device__ __forceinline__ void cp16(uint32_t dst, const void* src) {
    asm volatile("cp.async.cg.shared.global [%0], [%1], 16;"
                 :: "r"(dst), "l"(src) : "memory");
}
#define CP_COMMIT()  asm volatile("cp.async.commit_group;" ::: "memory")
#define CP_WAIT(n)   asm volatile("cp.async.wait_group %0;" :: "n"(n) : "memory")

// m16n8k8 row.col tf32 mma: D = A*B + C (C==D accumulators)
__device__ __forceinline__ void mma8(float* c, const uint32_t* a,
                                     uint32_t b0, uint32_t b1) {
    asm volatile(
        "mma.sync.aligned.m16n8k8.row.col.f32.tf32.tf32.f32 "
        "{%0,%1,%2,%3}, {%4,%5,%6,%7}, {%8,%9}, {%0,%1,%2,%3};"
        : "+f"(c[0]), "+f"(c[1]), "+f"(c[2]), "+f"(c[3])
        : "r"(a[0]), "r"(a[1]), "r"(a[2]), "r"(a[3]), "r"(b0), "r"(b1));
}

// ---------------------------------------------------------------------------
// Kernel: one CTA per batch; 256 threads = 8 warps in a 4(M) x 2(N) grid.
// Warp tile: m32 x n64.  CTA tile: 128(M) x 128(N), K chunked by 32.
// ---------------------------------------------------------------------------
__global__ void __launch_bounds__(256, 2)
hrpa_kernel(const float* __restrict__ patch,   // (B, N, C)
            const float* __restrict__ word,    // (B, M, C)
            const float* __restrict__ mask,    // (B, N)
            float* __restrict__ out)           // (B, 1)
{
    extern __shared__ float sm[];
    const uint32_t smb = smem_u32(sm);

    const int tid  = threadIdx.x;
    const int lane = tid & 31;
    const int w    = tid >> 5;
    const int wm   = w & 3;        // 0..3 (M direction)
    const int wn   = w >> 2;       // 0..1 (N direction)
    const int g    = lane >> 2;    // groupID 0..7
    const int tig  = lane & 3;     // threadID-in-group 0..3
    const int b    = blockIdx.x;

    // ---- mask -> smem, accumulate mask sum ----
    float masksum = 0.f;
    for (int i = tid; i < N_; i += 256) {
        float m = mask[b * N_ + i];
        sm[OFF_MASK + i] = m;
        masksum += m;
    }

    // ---- tile-load addressing: 32 rows/pass, 4 passes, 8 vec4 per row ----
    const int lrow = tid >> 3;  // 0..31
    const int lvec = tid & 7;   // 0..7

    const float* wbase = word  + (size_t)b * M_ * C_;
    const float* pbase = patch + (size_t)b * N_ * C_;

    auto issue_load = [&](int gq, int buf) {
        const int nt = gq >> 4, kc = gq & 15, k0 = kc * KC;
        const float* asrc = wbase + k0;
        const float* bsrc = pbase + (size_t)(nt * NTILE) * C_ + k0;
        const uint32_t ab = smb + (uint32_t)(buf * BUF_FLOATS + OFF_A0) * 4u;
        const uint32_t bb = smb + (uint32_t)(buf * BUF_FLOATS + OFF_B0) * 4u;
        #pragma unroll
        for (int p = 0; p < 4; p++) {
            const int r = p * 32 + lrow;
            cp16(ab + (uint32_t)(r * SP + lvec * 4) * 4u, asrc + (size_t)r * C_ + lvec * 4);
            cp16(bb + (uint32_t)(r * SP + lvec * 4) * 4u, bsrc + (size_t)r * C_ + lvec * 4);
        }
    };

    issue_load(0, 0);
    CP_COMMIT();

    float rmax[4] = {-3.0e38f, -3.0e38f, -3.0e38f, -3.0e38f}; // rows g, g+8 per mtile
    float colsum = 0.f;

    for (int nt = 0; nt < NTILES; nt++) {
        float acc[2][8][4];
        #pragma unroll
        for (int mt = 0; mt < 2; mt++)
            #pragma unroll
            for (int j = 0; j < 8; j++)
                #pragma unroll
                for (int q = 0; q < 4; q++) acc[mt][j][q] = 0.f;

        for (int kc = 0; kc < KCH; kc++) {
            const int gq  = nt * KCH + kc;
            const int buf = gq & 1;
            if (gq + 1 < GTOT) {
                issue_load(gq + 1, (gq + 1) & 1);
                CP_COMMIT();
                CP_WAIT(1);
            } else {
                CP_WAIT(0);
            }
            __syncthreads();

            const float* As = sm + buf * BUF_FLOATS + OFF_A0;
            const float* Bs = sm + buf * BUF_FLOATS + OFF_B0;

            #pragma unroll
            for (int ks = 0; ks < 4; ks++) {
                const int k0 = ks * 8;
                uint32_t a[2][4];
                #pragma unroll
                for (int mt = 0; mt < 2; mt++) {
                    const int m0 = wm * 32 + mt * 16;
                    a[mt][0] = __float_as_uint(As[(m0 +     g) * SP + k0 + tig    ]);
                    a[mt][1] = __float_as_uint(As[(m0 + 8 + g) * SP + k0 + tig    ]);
                    a[mt][2] = __float_as_uint(As[(m0 +     g) * SP + k0 + tig + 4]);
                    a[mt][3] = __float_as_uint(As[(m0 + 8 + g) * SP + k0 + tig + 4]);
                }
                #pragma unroll
                for (int j = 0; j < 8; j++) {
                    const int nb = wn * 64 + j * 8;
                    const uint32_t b0 = __float_as_uint(Bs[(nb + g) * SP + k0 + tig    ]);
                    const uint32_t b1 = __float_as_uint(Bs[(nb + g) * SP + k0 + tig + 4]);
                    mma8(acc[0][j], a[0], b0, b1);
                    mma8(acc[1][j], a[1], b0, b1);
                }
            }
            __syncthreads();
        }

        // ---- epilogue for this ntile ----
        // Thread owns rows {wm*32+mt*16+g, +8} and cols {wn*64+j*8+2tig, +1}.
        float colpart[16];
        #pragma unroll
        for (int j = 0; j < 8; j++) {
            #pragma unroll
            for (int cc = 0; cc < 2; cc++) {
                const int col = wn * 64 + j * 8 + 2 * tig + cc;
                const float pen = 1000.f * (1.f - sm[OFF_MASK + nt * NTILE + col]);
                float vmax = -3.0e38f;
                #pragma unroll
                for (int mt = 0; mt < 2; mt++) {
                    float v0 = acc[mt][j][cc];      // row m0+g
                    float v1 = acc[mt][j][cc + 2];  // row m0+8+g
                    v0 = v0 > 0.f ? v0 : 0.1f * v0;
                    v1 = v1 > 0.f ? v1 : 0.1f * v1;
                    rmax[mt * 2 + 0] = fmaxf(rmax[mt * 2 + 0], v0 - pen);
                    rmax[mt * 2 + 1] = fmaxf(rmax[mt * 2 + 1], v1 - pen);
                    vmax = fmaxf(vmax, fmaxf(v0, v1));
                }
                colpart[j * 2 + cc] = vmax;
            }
        }
        // column max across the 8 groups (lanes differing in g)
        #pragma unroll
        for (int off = 4; off <= 16; off <<= 1)
            #pragma unroll
            for (int i = 0; i < 16; i++)
                colpart[i] = fmaxf(colpart[i], __shfl_xor_sync(0xffffffffu, colpart[i], off));
        if (g == 0) {
            #pragma unroll
            for (int j = 0; j < 8; j++)
                #pragma unroll
                for (int cc = 0; cc < 2; cc++)
                    sm[OFF_COLW + wm * 128 + wn * 64 + j * 8 + 2 * tig + cc] =
                        colpart[j * 2 + cc];
        }
        __syncthreads();
        if (tid < 128) {
            const float cm = fmaxf(fmaxf(sm[OFF_COLW + tid], sm[OFF_COLW + 128 + tid]),
                                   fmaxf(sm[OFF_COLW + 256 + tid], sm[OFF_COLW + 384 + tid]));
            colsum += cm * sm[OFF_MASK + nt * NTILE + tid];
        }
        __syncthreads();
    }

    // ---- row-max combine ----
    #pragma unroll
    for (int off = 1; off <= 2; off <<= 1)
        #pragma unroll
        for (int i = 0; i < 4; i++)
            rmax[i] = fmaxf(rmax[i], __shfl_xor_sync(0xffffffffu, rmax[i], off));
    if (tig == 0) {
        #pragma unroll
        for (int mt = 0; mt < 2; mt++) {
            sm[OFF_ROWRED + (wm * 32 + mt * 16 +     g) * 2 + wn] = rmax[mt * 2 + 0];
            sm[OFF_ROWRED + (wm * 32 + mt * 16 + 8 + g) * 2 + wn] = rmax[mt * 2 + 1];
        }
    }
    __syncthreads();

    float rpart = 0.f;
    if (tid < 128)
        rpart = fmaxf(sm[OFF_ROWRED + tid * 2], sm[OFF_ROWRED + tid * 2 + 1]);

    // ---- block reduction of rpart / colsum / masksum ----
    #pragma unroll
    for (int off = 16; off > 0; off >>= 1) {
        rpart   += __shfl_down_sync(0xffffffffu, rpart,   off);
        colsum  += __shfl_down_sync(0xffffffffu, colsum,  off);
        masksum += __shfl_down_sync(0xffffffffu, masksum, off);
    }
    if (lane == 0) {
        sm[OFF_RED + w * 4 + 0] = rpart;
        sm[OFF_RED + w * 4 + 1] = colsum;
        sm[OFF_RED + w * 4 + 2] = masksum;
    }
    __syncthreads();
    if (tid == 0) {
        float rs = 0.f, cs = 0.f, ms = 0.f;
        #pragma unroll
        for (int i = 0; i < 8; i++) {
            rs += sm[OFF_RED + i * 4 + 0];
            cs += sm[OFF_RED + i * 4 + 1];
            ms += sm[OFF_RED + i * 4 + 2];
        }
        out[b] = rs * (1.f / 128.f) + cs / (ms + 1e-8f);
    }
}

// ---------------------------------------------------------------------------
// Host launch
// ---------------------------------------------------------------------------
extern "C" void kernel_launch(void* const* d_in, const int* in_sizes, int n_in,
                              void* d_out, int out_size)
{
    (void)in_sizes; (void)n_in; (void)out_size;
    const float* patch = (const float*)d_in[0];  // (B, N, C)
    const float* word  = (const float*)d_in[1];  // (B, M, C)
    const float* mask  = (const float*)d_in[2];  // (B, N)
    float* out = (float*)d_out;                  // (B, 1)

    cudaFuncSetAttribute(hrpa_kernel,
                         cudaFuncAttributeMaxDynamicSharedMemorySize, SMEM_BYTES);
    hrpa_kernel<<<B_, 256, SMEM_BYTES>>>(patch, word, mask, out);
}

// round 5
// speedup vs baseline: 1.3921x; 1.3921x over previous
#include <cuda_runtime.h>
#include <cuda_fp16.h>
#include <cstdint>
#include <cstddef>

// ---------------------------------------------------------------------------
// Problem constants
// ---------------------------------------------------------------------------
constexpr int B_ = 256;   // batches
constexpr int N_ = 1024;  // patches
constexpr int M_ = 128;   // words
constexpr int C_ = 512;   // channels (K)

constexpr int NTILE  = 128;          // patch tile
constexpr int NTILES = N_ / NTILE;   // 8
constexpr int KC     = 32;           // K chunk (fp32 elements)
constexpr int KCH    = C_ / KC;      // 16
constexpr int GTOT   = NTILES * KCH; // 128 chunks
constexpr int SPH    = 40;           // smem row stride in halfs (32 + 8 pad) = 80 B

// Stage buffer geometry (bytes)
constexpr int A_HALFS     = 128 * SPH;              // 5120 halfs = 10240 B
constexpr int BUF_BYTES   = 2 * A_HALFS * 2;        // A + B = 20480 B per buffer
constexpr int OFF_Bt      = A_HALFS * 2;            // B tile offset inside buffer

// Float-indexed regions after the two stage buffers (2 * 20480 = 40960 B)
constexpr int MASKF   = 40960 / 4;        // 1024 floats
constexpr int COLWF   = MASKF + 1024;     // 4 x 128 floats
constexpr int ROWREDF = COLWF + 512;      // 128 x 2 floats
constexpr int REDF    = ROWREDF + 256;    // 32 floats
constexpr int SMEM_BYTES = (REDF + 32) * 4;   // 48256

// ---------------------------------------------------------------------------
// Helpers
// ---------------------------------------------------------------------------
__device__ __forceinline__ uint32_t smem_u32(const void* p) {
    uint32_t a;
    asm("{ .reg .u64 t; cvta.to.shared.u64 t, %1; cvt.u32.u64 %0, t; }"
        : "=r"(a) : "l"(p));
    return a;
}

__device__ __forceinline__ void ldm4(uint32_t* r, uint32_t addr) {
    asm volatile("ldmatrix.sync.aligned.m8n8.x4.shared.b16 {%0,%1,%2,%3}, [%4];"
                 : "=r"(r[0]), "=r"(r[1]), "=r"(r[2]), "=r"(r[3]) : "r"(addr));
}

// m16n8k16 row.col fp16 mma, fp32 accumulate (C==D)
__device__ __forceinline__ void mma16(float* c, const uint32_t* a,
                                      uint32_t b0, uint32_t b1) {
    asm volatile(
        "mma.sync.aligned.m16n8k16.row.col.f32.f16.f16.f32 "
        "{%0,%1,%2,%3}, {%4,%5,%6,%7}, {%8,%9}, {%0,%1,%2,%3};"
        : "+f"(c[0]), "+f"(c[1]), "+f"(c[2]), "+f"(c[3])
        : "r"(a[0]), "r"(a[1]), "r"(a[2]), "r"(a[3]), "r"(b0), "r"(b1));
}

// ---------------------------------------------------------------------------
// Kernel: one CTA per batch; 256 threads = 8 warps (4 M x 2 N).
// Warp tile m32 x n64. CTA tile 128(M) x 128(N). K chunked by 32 (2 x k16).
// fp16 operands (converted in the loader), fp32 accumulators.
// ---------------------------------------------------------------------------
__global__ void __launch_bounds__(256, 2)
hrpa_kernel(const float* __restrict__ patch,   // (B, N, C)
            const float* __restrict__ word,    // (B, M, C)
            const float* __restrict__ mask,    // (B, N)
            float* __restrict__ out)           // (B, 1)
{
    extern __shared__ char smc[];
    float* fsm = reinterpret_cast<float*>(smc);
    const uint32_t smb = smem_u32(smc);

    const int tid  = threadIdx.x;
    const int lane = tid & 31;
    const int w    = tid >> 5;
    const int wm   = w & 3;        // M direction (rows wm*32 .. +31)
    const int wn   = w >> 2;       // N direction (cols wn*64 .. +63)
    const int g    = lane >> 2;    // quad group 0..7
    const int tig  = lane & 3;     // thread in group
    const int b    = blockIdx.x;

    // ldmatrix per-thread offsets (half units, before m0/n0/ks terms)
    const int mi = lane >> 3, r8 = lane & 7;
    const int aoff = (((mi & 1) << 3) + r8) * SPH + ((mi >> 1) << 3);
    const int boff = (((mi >> 1) << 3) + r8) * SPH + ((mi & 1) << 3);

    const float* wbase = word  + (size_t)b * M_ * C_;
    const float* pbase = patch + (size_t)b * N_ * C_;

    // loader slot mapping: 4 A-slots + 4 B-slots per thread
    // slot = p*256 + tid -> row = slot>>3 (0..127), v = slot&7 (vec4 index)
    const int lr = tid >> 3;   // base row for p stepping (+32 per p)
    const int lv = tid & 7;

    // ---- mask -> smem, accumulate mask sum ----
    float masksum = 0.f;
    for (int i = tid; i < N_; i += 256) {
        float m = mask[b * N_ + i];
        fsm[MASKF + i] = m;
        masksum += m;
    }

    auto load_regs = [&](int gq, float4* stA, float4* stB) {
        const int nt = gq >> 4;
        const int k0 = (gq & 15) * KC;
        #pragma unroll
        for (int p = 0; p < 4; p++) {
            const int r = p * 32 + lr;
            stA[p] = *(const float4*)(wbase + (size_t)r * C_ + k0 + lv * 4);
            stB[p] = *(const float4*)(pbase + (size_t)(nt * NTILE + r) * C_ + k0 + lv * 4);
        }
    };
    auto sts_stage = [&](int buf, const float4* stA, const float4* stB) {
        char* base = smc + buf * BUF_BYTES;
        #pragma unroll
        for (int p = 0; p < 4; p++) {
            const int r = p * 32 + lr;
            const int hidx = r * SPH + lv * 4;
            __half2 a0 = __floats2half2_rn(stA[p].x, stA[p].y);
            __half2 a1 = __floats2half2_rn(stA[p].z, stA[p].w);
            *(uint2*)(base + hidx * 2) =
                make_uint2(*(uint32_t*)&a0, *(uint32_t*)&a1);
            __half2 b0 = __floats2half2_rn(stB[p].x, stB[p].y);
            __half2 b1 = __floats2half2_rn(stB[p].z, stB[p].w);
            *(uint2*)(base + OFF_Bt + hidx * 2) =
                make_uint2(*(uint32_t*)&b0, *(uint32_t*)&b1);
        }
    };

    // prologue: chunk 0 -> buffer 0
    {
        float4 sA[4], sB[4];
        load_regs(0, sA, sB);
        sts_stage(0, sA, sB);
    }
    __syncthreads();

    float rmax[4] = {-3.0e38f, -3.0e38f, -3.0e38f, -3.0e38f};
    float colsum = 0.f;

    for (int nt = 0; nt < NTILES; nt++) {
        float acc[2][8][4];
        #pragma unroll
        for (int mt = 0; mt < 2; mt++)
            #pragma unroll
            for (int j = 0; j < 8; j++)
                #pragma unroll
                for (int q = 0; q < 4; q++) acc[mt][j][q] = 0.f;

        for (int kc = 0; kc < KCH; kc++) {
            const int gq  = nt * KCH + kc;
            const int buf = gq & 1;
            const bool more = (gq + 1 < GTOT);

            // prefetch next chunk into registers (independent of MMAs below)
            float4 sA[4], sB[4];
            if (more) load_regs(gq + 1, sA, sB);

            // ---- MMAs on chunk gq from smem[buf] ----
            const uint32_t abase = smb + buf * BUF_BYTES;
            const uint32_t bbase = abase + OFF_Bt;
            #pragma unroll
            for (int ks = 0; ks < 2; ks++) {
                uint32_t A0[4], A1[4];
                ldm4(A0, abase + (uint32_t)(((wm * 32     ) * SPH) + aoff + ks * 16) * 2);
                ldm4(A1, abase + (uint32_t)(((wm * 32 + 16) * SPH) + aoff + ks * 16) * 2);
                #pragma unroll
                for (int jj = 0; jj < 4; jj++) {
                    uint32_t Bf[4];
                    ldm4(Bf, bbase + (uint32_t)(((wn * 64 + jj * 16) * SPH) + boff + ks * 16) * 2);
                    mma16(acc[0][jj * 2    ], A0, Bf[0], Bf[1]);
                    mma16(acc[1][jj * 2    ], A1, Bf[0], Bf[1]);
                    mma16(acc[0][jj * 2 + 1], A0, Bf[2], Bf[3]);
                    mma16(acc[1][jj * 2 + 1], A1, Bf[2], Bf[3]);
                }
            }

            // store next chunk to the other buffer, then one sync
            if (more) sts_stage(buf ^ 1, sA, sB);
            __syncthreads();
        }

        // ---- epilogue for this ntile ----
        // Thread owns rows {wm*32+mt*16+g, +8}, cols {wn*64+j*8+2tig, +1}.
        float colpart[16];
        #pragma unroll
        for (int j = 0; j < 8; j++) {
            #pragma unroll
            for (int cc = 0; cc < 2; cc++) {
                const int col = wn * 64 + j * 8 + 2 * tig + cc;
                const float pen = 1000.f * (1.f - fsm[MASKF + nt * NTILE + col]);
                float vmax = -3.0e38f;
                #pragma unroll
                for (int mt = 0; mt < 2; mt++) {
                    float v0 = acc[mt][j][cc];      // row m0+g
                    float v1 = acc[mt][j][cc + 2];  // row m0+8+g
                    v0 = v0 > 0.f ? v0 : 0.1f * v0;
                    v1 = v1 > 0.f ? v1 : 0.1f * v1;
                    rmax[mt * 2 + 0] = fmaxf(rmax[mt * 2 + 0], v0 - pen);
                    rmax[mt * 2 + 1] = fmaxf(rmax[mt * 2 + 1], v1 - pen);
                    vmax = fmaxf(vmax, fmaxf(v0, v1));
                }
                colpart[j * 2 + cc] = vmax;
            }
        }
        // column max across the 8 quad-groups (lanes differing in g)
        #pragma unroll
        for (int off = 4; off <= 16; off <<= 1)
            #pragma unroll
            for (int i = 0; i < 16; i++)
                colpart[i] = fmaxf(colpart[i], __shfl_xor_sync(0xffffffffu, colpart[i], off));
        if (g == 0) {
            #pragma unroll
            for (int j = 0; j < 8; j++)
                #pragma unroll
                for (int cc = 0; cc < 2; cc++)
                    fsm[COLWF + wm * 128 + wn * 64 + j * 8 + 2 * tig + cc] =
                        colpart[j * 2 + cc];
        }
        __syncthreads();
        if (tid < 128) {
            const float cm = fmaxf(fmaxf(fsm[COLWF + tid], fsm[COLWF + 128 + tid]),
                                   fmaxf(fsm[COLWF + 256 + tid], fsm[COLWF + 384 + tid]));
            colsum += cm * fsm[MASKF + nt * NTILE + tid];
        }
        __syncthreads();
    }

    // ---- row-max combine (within quad, then across warps) ----
    #pragma unroll
    for (int off = 1; off <= 2; off <<= 1)
        #pragma unroll
        for (int i = 0; i < 4; i++)
            rmax[i] = fmaxf(rmax[i], __shfl_xor_sync(0xffffffffu, rmax[i], off));
    if (tig == 0) {
        #pragma unroll
        for (int mt = 0; mt < 2; mt++) {
            fsm[ROWREDF + (wm * 32 + mt * 16 +     g) * 2 + wn] = rmax[mt * 2 + 0];
            fsm[ROWREDF + (wm * 32 + mt * 16 + 8 + g) * 2 + wn] = rmax[mt * 2 + 1];
        }
    }
    __syncthreads();

    float rpart = 0.f;
    if (tid < 128)
        rpart = fmaxf(fsm[ROWREDF + tid * 2], fsm[ROWREDF + tid * 2 + 1]);

    // ---- block reduction of rpart / colsum / masksum ----
    #pragma unroll
    for (int off = 16; off > 0; off >>= 1) {
        rpart   += __shfl_down_sync(0xffffffffu, rpart,   off);
        colsum  += __shfl_down_sync(0xffffffffu, colsum,  off);
        masksum += __shfl_down_sync(0xffffffffu, masksum, off);
    }
    if (lane == 0) {
        fsm[REDF + w * 4 + 0] = rpart;
        fsm[REDF + w * 4 + 1] = colsum;
        fsm[REDF + w * 4 + 2] = masksum;
    }
    __syncthreads();
    if (tid == 0) {
        float rs = 0.f, cs = 0.f, ms = 0.f;
        #pragma unroll
        for (int i = 0; i < 8; i++) {
            rs += fsm[REDF + i * 4 + 0];
            cs += fsm[REDF + i * 4 + 1];
            ms += fsm[REDF + i * 4 + 2];
        }
        out[b] = rs * (1.f / 128.f) + cs / (ms + 1e-8f);
    }
}

// ---------------------------------------------------------------------------
// Host launch
// ---------------------------------------------------------------------------
extern "C" void kernel_launch(void* const* d_in, const int* in_sizes, int n_in,
                              void* d_out, int out_size)
{
    (void)in_sizes; (void)n_in; (void)out_size;
    const float* patch = (const float*)d_in[0];  // (B, N, C)
    const float* word  = (const float*)d_in[1];  // (B, M, C)
    const float* mask  = (const float*)d_in[2];  // (B, N)
    float* out = (float*)d_out;                  // (B, 1)

    cudaFuncSetAttribute(hrpa_kernel,
                         cudaFuncAttributeMaxDynamicSharedMemorySize, SMEM_BYTES);
    hrpa_kernel<<<B_, 256, SMEM_BYTES>>>(patch, word, mask, out);
}